// round 10
// baseline (speedup 1.0000x reference)
#include <cuda_runtime.h>
#include <stdint.h>

// core0: (1,50,8,16) A[v0][e0][r1] ; core1: (16,50,4,16) B[r1][v1][e1][r2]
// core2: (16,80,4,1) C[r2][v2][e2] ; indices: 8192 of vocab 200000=(50,50,80)
// out[n][e0*16+e1*4+e2] fp32

#define NV1 50
#define NV2 80
#define RANK 16
#define NIDX 8192
#define NPAIRS (NV1 * NV2)      // 4000
#define HBLOCKS (NPAIRS / 8)    // 500
#define GRID 1024

__device__ float g_H[NPAIRS * RANK * 16];   // 4 MB, L2-resident
__device__ int   g_arrive = 0;
__device__ int   g_done   = 0;

__device__ __forceinline__ void cpasync16(uint32_t dst, const void* src) {
    asm volatile("cp.async.cg.shared.global [%0], [%1], 16;" :: "r"(dst), "l"(src) : "memory");
}

// Single persistent kernel. launch_bounds(256,7): regs<=36, smem 18.7KB ->
// 7 blocks/SM -> 148*7 = 1036 resident slots >= 1024 blocks => spin is safe.
__global__ __launch_bounds__(256, 7) void tt_all(
    const void*  __restrict__ idx_raw,
    const float* __restrict__ core0,
    const float* __restrict__ core1,
    const float* __restrict__ core2,
    float* __restrict__ out)
{
    __shared__ __align__(16) float  sB[16 * 68];     // phase1: B[:,v1] padded
    __shared__ __align__(16) float4 sc[8][16];       // phase1: C slices
    __shared__ __align__(16) float4 sh[8][96];       // phase2: A+H tiles

    const int tid  = threadIdx.x;
    const int w    = tid >> 5;
    const int lane = tid & 31;
    const int bid  = blockIdx.x;

    // dtype sniff on the INPUT buffer (read-only => safe): int64 high words all 0
    const int* i32 = (const int*)idx_raw;
    const bool is64 = __all_sync(0xffffffffu, i32[2 * lane + 1] == 0);
    const long long* i64 = (const long long*)idx_raw;

    // ======================= Phase 1: blocks [0,500) build H ==================
    if (bid < HBLOCKS) {
        const int pair0 = bid * 8;                   // 8 pairs, same v1 (80%8==0)
        const int v1    = pair0 / NV2;
        const int v2    = (pair0 - v1 * NV2) + w;
        {
            const int r1 = tid >> 4;
            const int c4 = tid & 15;
            const float4 b = __ldg((const float4*)(core1 + ((size_t)r1 * NV1 + v1) * 64) + c4);
            *(float4*)&sB[r1 * 68 + c4 * 4] = b;
        }
        if (lane < RANK)
            sc[w][lane] = __ldg((const float4*)(core2 + ((size_t)lane * NV2 + v2) * 4));
        __syncthreads();

        float* hout = g_H + (size_t)(v1 * NV2 + v2) * (RANK * 16);
#pragma unroll
        for (int pass = 0; pass < 2; ++pass) {
            const int j  = lane + 32 * pass;
            const int r1 = j >> 2;
            const int e1 = j & 3;
            const float* bp = &sB[r1 * 68 + e1 * 16];
            float4 acc = make_float4(0.f, 0.f, 0.f, 0.f);
#pragma unroll
            for (int r2 = 0; r2 < RANK; ++r2) {
                const float bbv = bp[r2];
                const float4 c4 = sc[w][r2];
                acc.x = fmaf(bbv, c4.x, acc.x);
                acc.y = fmaf(bbv, c4.y, acc.y);
                acc.z = fmaf(bbv, c4.z, acc.z);
                acc.w = fmaf(bbv, c4.w, acc.w);
            }
            ((float4*)hout)[j] = acc;                // plain store -> L2
        }
        __syncthreads();
        if (tid == 0) { __threadfence(); atomicAdd(&g_arrive, 1); }
    }

    // ======================= Grid barrier ====================================
    if (tid == 0) {
        while (*(volatile int*)&g_arrive < HBLOCKS) __nanosleep(32);
        __threadfence();
        // last of all 1024 blocks resets state for the next graph replay
        if (atomicAdd(&g_done, 1) == GRID - 1) {
            atomicExch(&g_arrive, 0);
            atomicExch(&g_done, 0);
        }
    }
    __syncthreads();

    // ======================= Phase 2: gather, 1 index/warp ===================
    const int idx = bid * 8 + w;                     // 0..8191

    // Warp-uniform scalar load of the raw index (input buffer, nc-safe),
    // then two constant-divides (mul-hi) to decompose.
    const int iv = is64 ? (int)i64[idx] : i32[idx];
    const int v0 = iv / NPAIRS;
    const int p  = iv - v0 * NPAIRS;

    const float4* At = (const float4*)core0 + (size_t)v0 * 32;
    const float4* Ht = (const float4*)g_H   + (size_t)p * 64;

    // 3 in-flight 16B copies/lane, no destination registers; H via L2 (coherent).
    const uint32_t sbase = (uint32_t)__cvta_generic_to_shared(&sh[w][0]);
    cpasync16(sbase + lane * 16,        At + lane);
    cpasync16(sbase + (32 + lane) * 16, Ht + lane);
    cpasync16(sbase + (64 + lane) * 16, Ht + lane + 32);
    asm volatile("cp.async.commit_group;" ::: "memory");
    asm volatile("cp.async.wait_group 0;"  ::: "memory");
    __syncwarp();

    const int e0 = lane >> 2;
    const int q  = lane & 3;

    float a[RANK];
#pragma unroll
    for (int k = 0; k < 4; ++k) {
        const float4 t4 = sh[w][e0 * 4 + k];
        a[4 * k + 0] = t4.x; a[4 * k + 1] = t4.y; a[4 * k + 2] = t4.z; a[4 * k + 3] = t4.w;
    }

    float4 acc = make_float4(0.f, 0.f, 0.f, 0.f);
#pragma unroll
    for (int r1 = 0; r1 < RANK; ++r1) {
        const float4 h = sh[w][32 + r1 * 4 + q];
        acc.x = fmaf(a[r1], h.x, acc.x);
        acc.y = fmaf(a[r1], h.y, acc.y);
        acc.z = fmaf(a[r1], h.z, acc.z);
        acc.w = fmaf(a[r1], h.w, acc.w);
    }

    ((float4*)(out + (size_t)idx * 128))[lane] = acc;
}

// Inputs (metadata order): indices, core0, core1, core2
extern "C" void kernel_launch(void* const* d_in, const int* in_sizes, int n_in,
                              void* d_out, int out_size)
{
    const void*  indices = d_in[0];
    const float* core0   = (const float*)d_in[1];
    const float* core1   = (const float*)d_in[2];
    const float* core2   = (const float*)d_in[3];
    float* out = (float*)d_out;

    tt_all<<<GRID, 256>>>(indices, core0, core1, core2, out);
}

// round 11
// speedup vs baseline: 1.1658x; 1.1658x over previous
#include <cuda_runtime.h>
#include <stdint.h>

// core0: (1,50,8,16) A[v0][e0][r1] ; core1: (16,50,4,16) B[r1][v1][e1][r2]
// core2: (16,80,4,1) C[r2][v2][e2] ; indices: 8192 of vocab 200000=(50,50,80)
// out[n][e0*16+e1*4+e2] fp32

#define NV1 50
#define NV2 80
#define RANK 16
#define NIDX 8192
#define NPAIRS (NV1 * NV2)      // 4000

// H[(v1*80+v2)][r1][e1*4+e2]: 4 MB, L2-resident
__device__ float g_H[NPAIRS * RANK * 16];

// ---------------------------------------------------------------------------
// Kernel 1: block = 8 pairs sharing v1 (80 % 8 == 0). B[:,v1] staged once.
// ---------------------------------------------------------------------------
__global__ __launch_bounds__(256) void tt_build_H(
    const float* __restrict__ core1,
    const float* __restrict__ core2)
{
    __shared__ __align__(16) float  sB[16 * 68];
    __shared__ __align__(16) float4 sc[8][16];

    const int tid  = threadIdx.x;
    const int w    = tid >> 5;
    const int lane = tid & 31;
    const int pair0 = blockIdx.x * 8;
    const int v1    = pair0 / NV2;
    const int v2    = (pair0 - v1 * NV2) + w;

    {
        const int r1 = tid >> 4;
        const int c4 = tid & 15;
        const float4 b = __ldg((const float4*)(core1 + ((size_t)r1 * NV1 + v1) * 64) + c4);
        *(float4*)&sB[r1 * 68 + c4 * 4] = b;
    }
    if (lane < RANK)
        sc[w][lane] = __ldg((const float4*)(core2 + ((size_t)lane * NV2 + v2) * 4));
    __syncthreads();

    float* hout = g_H + (size_t)(v1 * NV2 + v2) * (RANK * 16);

#pragma unroll
    for (int pass = 0; pass < 2; ++pass) {
        const int j  = lane + 32 * pass;
        const int r1 = j >> 2;
        const int e1 = j & 3;
        const float* bp = &sB[r1 * 68 + e1 * 16];
        float4 acc = make_float4(0.f, 0.f, 0.f, 0.f);
#pragma unroll
        for (int r2 = 0; r2 < RANK; ++r2) {
            const float bbv = bp[r2];
            const float4 c4 = sc[w][r2];
            acc.x = fmaf(bbv, c4.x, acc.x);
            acc.y = fmaf(bbv, c4.y, acc.y);
            acc.z = fmaf(bbv, c4.z, acc.z);
            acc.w = fmaf(bbv, c4.w, acc.w);
        }
        ((float4*)hout)[j] = acc;
    }
}

// ---------------------------------------------------------------------------
// Kernel 2: warp per index; NO shared memory. 3 coalesced LDG.128 put the
// whole A tile (av) and H tile (h0,h1) in the warp's registers; operands are
// then fetched with shuffles. Lane l: e0=l>>2, q=l&3 owns out[l*4 .. l*4+3].
//   a[r1]          = shfl(av component (r1&3),  src (l&28)+(r1>>2))
//   H[r1][q*4..+3] = shfl(h{0,1} (r1<8 ? h0:h1), src 4*(r1&7)+q)
// ---------------------------------------------------------------------------
__global__ __launch_bounds__(256) void tt_gather(
    const void* __restrict__ idx_raw,
    const float* __restrict__ core0,
    float* __restrict__ out)
{
    const int gtid = blockIdx.x * blockDim.x + threadIdx.x;
    const int warp = gtid >> 5;
    const int lane = threadIdx.x & 31;

    // dtype sniff: int64 vs int32 (values < 2e5 -> int64 high words all zero)
    const int* i32 = (const int*)idx_raw;
    const bool is64 = __all_sync(0xffffffffu, i32[2 * lane + 1] == 0);

    int iv;
    if (is64) iv = (int)((const long long*)idx_raw)[warp];   // warp-uniform
    else      iv = i32[warp];

    const int v0 = iv / NPAIRS;
    const int p  = iv - v0 * NPAIRS;

    // 3 independent, dedup'd, coalesced tile loads -> registers.
    const float4 av = __ldg((const float4*)core0 + (size_t)v0 * 32 + lane);
    const float4* Ht = (const float4*)g_H + (size_t)p * 64;
    const float4 h0 = __ldg(&Ht[lane]);
    const float4 h1 = __ldg(&Ht[lane + 32]);

    const int q    = lane & 3;
    const int abase = lane & 28;          // 4*e0

    float4 acc = make_float4(0.f, 0.f, 0.f, 0.f);

#pragma unroll
    for (int r1 = 0; r1 < RANK; ++r1) {
        // a[r1]: component r1&3 (compile-time) from lane abase + (r1>>2)
        float asrc;
        switch (r1 & 3) {
            case 0: asrc = av.x; break;
            case 1: asrc = av.y; break;
            case 2: asrc = av.z; break;
            default: asrc = av.w; break;
        }
        const float ar = __shfl_sync(0xffffffffu, asrc, abase + (r1 >> 2));

        // H[r1][q*4..+3]: float4 from lane 4*(r1&7)+q, in h0 (r1<8) or h1.
        const int hsrc = 4 * (r1 & 7) + q;
        float hx, hy, hz, hw;
        if (r1 < 8) {
            hx = __shfl_sync(0xffffffffu, h0.x, hsrc);
            hy = __shfl_sync(0xffffffffu, h0.y, hsrc);
            hz = __shfl_sync(0xffffffffu, h0.z, hsrc);
            hw = __shfl_sync(0xffffffffu, h0.w, hsrc);
        } else {
            hx = __shfl_sync(0xffffffffu, h1.x, hsrc);
            hy = __shfl_sync(0xffffffffu, h1.y, hsrc);
            hz = __shfl_sync(0xffffffffu, h1.z, hsrc);
            hw = __shfl_sync(0xffffffffu, h1.w, hsrc);
        }

        acc.x = fmaf(ar, hx, acc.x);
        acc.y = fmaf(ar, hy, acc.y);
        acc.z = fmaf(ar, hz, acc.z);
        acc.w = fmaf(ar, hw, acc.w);
    }

    ((float4*)(out + (size_t)warp * 128))[lane] = acc;
}

// Inputs (metadata order): indices, core0, core1, core2
extern "C" void kernel_launch(void* const* d_in, const int* in_sizes, int n_in,
                              void* d_out, int out_size)
{
    const void*  indices = d_in[0];
    const float* core0   = (const float*)d_in[1];
    const float* core1   = (const float*)d_in[2];
    const float* core2   = (const float*)d_in[3];
    float* out = (float*)d_out;

    tt_build_H<<<NPAIRS / 8, 256>>>(core1, core2);
    tt_gather<<<(NIDX * 32) / 256, 256>>>(indices, core0, out);
}